// round 5
// baseline (speedup 1.0000x reference)
#include <cuda_runtime.h>
#include <stdint.h>

#define D_    64
#define H_    32
#define W_    32
#define CIN_  128
#define COUT_ 128
#define NPIX  (D_*H_*W_)     // 65536
#define KOFF  1152
#define ROWS  4

// -------- scratch (no allocations allowed) --------
__device__ uint4 g_xb[NPIX];            // packed x bits: 128 bits / pixel
__device__ uint4 g_wb[D_*9*COUT_];      // packed w bits per (d,tap,cout)

// bytes of v are 0/1: returns b0 | b1<<1 | b2<<2 | b3<<3
__device__ __forceinline__ uint32_t nib(uint32_t v){
    return (v | (v >> 7) | (v >> 14) | (v >> 21)) & 0xFu;
}

// Pack x -> 128 bits/pixel. Dtype probe fused in (warp 0 scans first 4KB,
// L2-broadcast across blocks). Block = 256 threads = 8 warps; each warp
// packs 32 pixels with coalesced lane reads + ballot.
__global__ __launch_bounds__(256)
void pack_x_kernel(const uint8_t* __restrict__ x){
    __shared__ int mode_s;
    int tid = threadIdx.x;
    if (tid < 32){
        const uint4* p4 = reinterpret_cast<const uint4*>(x);
        int gt1 = 0, nz = 0, bf = 0;
        for (int i = tid; i < 256; i += 32){
            uint4 a = p4[i];
            uint32_t r[4] = {a.x, a.y, a.z, a.w};
            #pragma unroll
            for (int e = 0; e < 4; e++){
                uint32_t v = r[e];
                if (v & 0xFEFEFEFEu)            gt1 = 1;   // any byte >1
                if (v & 0xFFFFFF00u)            nz  = 1;   // nonzero off word-pos
                if (((v >> 8) & 0xFFu) == 0x3F) bf  = 1;   // bf16 signature
            }
        }
        gt1 = __reduce_or_sync(0xFFFFFFFFu, gt1);
        nz  = __reduce_or_sync(0xFFFFFFFFu, nz);
        bf  = __reduce_or_sync(0xFFFFFFFFu, bf);
        if (tid == 0) mode_s = (!gt1) ? (nz ? 0 : 1) : (bf ? 3 : 2);
    }
    __syncthreads();
    int mode = mode_s;                 // 0=uint8, 1=int32, 2=float32, 3=bf16

    if (mode == 1 || mode == 2){       // 4-byte 0/1 elems: ballot path
        int lane = tid & 31, wid = tid >> 5;
        int pbase = blockIdx.x * 256 + wid * 32;
        const uint32_t* xi = reinterpret_cast<const uint32_t*>(x);
        for (int j = 0; j < 32; j++){
            int p = pbase + j;
            uint32_t b[4];
            #pragma unroll
            for (int k = 0; k < 4; k++){
                uint32_t v = xi[(size_t)p * 128 + k * 32 + lane];
                b[k] = __ballot_sync(0xFFFFFFFFu, v != 0u);
            }
            if (lane == 0) g_xb[p] = make_uint4(b[0], b[1], b[2], b[3]);
        }
    } else if (mode == 0){             // uint8 bool: per-thread nib path
        int p = blockIdx.x * 256 + tid;
        const uint4* px = reinterpret_cast<const uint4*>(x) + (size_t)p * 8;
        uint32_t wd[4];
        #pragma unroll
        for (int k = 0; k < 4; k++){
            uint4 a = px[2*k], b = px[2*k+1];
            wd[k] = nib(a.x)        | (nib(a.y) << 4)  | (nib(a.z) << 8)  | (nib(a.w) << 12)
                  | (nib(b.x) << 16)| (nib(b.y) << 20) | (nib(b.z) << 24) | (nib(b.w) << 28);
        }
        g_xb[p] = make_uint4(wd[0], wd[1], wd[2], wd[3]);
    } else {                           // bf16 0/1
        int p = blockIdx.x * 256 + tid;
        const uint4* pb = reinterpret_cast<const uint4*>(x) + (size_t)p * 16;
        uint32_t wd[4];
        #pragma unroll
        for (int k = 0; k < 4; k++){
            uint32_t v = 0;
            #pragma unroll
            for (int q = 0; q < 4; q++){
                uint4 a = pb[k*4 + q];
                uint32_t r[4] = {a.x, a.y, a.z, a.w};
                #pragma unroll
                for (int e = 0; e < 4; e++){
                    v |= ((r[e] & 0x7FFFu)     ? 1u : 0u) << (q*8 + e*2 + 0);
                    v |= ((r[e] & 0x7FFF0000u) ? 1u : 0u) << (q*8 + e*2 + 1);
                }
            }
            wd[k] = v;
        }
        g_xb[p] = make_uint4(wd[0], wd[1], wd[2], wd[3]);
    }
}

// One block per (d,tap): coalesced load of 128(cin)x128(cout) float tile via
// smem, then BALLOT across cin-lanes packs 32 bits in one instruction.
__global__ __launch_bounds__(256)
void pack_w_kernel(const float* __restrict__ w){
    __shared__ float    tile[32][129];
    __shared__ uint32_t wword[4][128];
    int dt   = blockIdx.x;          // d*9 + tap
    int tid  = threadIdx.x;         // 256 threads
    int lane = tid & 31, warp = tid >> 5;
    const float* wp = w + (size_t)dt * (CIN_ * COUT_);
    #pragma unroll
    for (int chunk = 0; chunk < 4; chunk++){
        __syncthreads();
        #pragma unroll
        for (int e = 0; e < 16; e++){
            int idx = e * 256 + tid;                 // 32 cin-rows x 128 cout
            tile[idx >> 7][idx & 127] = wp[chunk * 4096 + idx];
        }
        __syncthreads();
        #pragma unroll
        for (int k = 0; k < 16; k++){
            int c = warp * 16 + k;                   // cout; lane = cin bit
            uint32_t b = __ballot_sync(0xFFFFFFFFu, tile[lane][c] != 0.0f);
            if (lane == 0) wword[chunk][c] = b;
        }
    }
    __syncthreads();
    if (tid < 128)
        g_wb[dt * COUT_ + tid] =
            make_uint4(wword[0][tid], wword[1][tid], wword[2][tid], wword[3][tid]);
}

// Conv via XOR identity: out = K - 2*sum_taps popc(x ^ w), exact with
// zero-filled halo. Thread co keeps 36 w-words in registers; x tile in smem
// (broadcast LDS.128); coalesced STG.
__global__ __launch_bounds__(256)
void conv_kernel(float* __restrict__ out){
    __shared__ uint4 xs[ROWS + 2][W_ + 2];
    int tid = threadIdx.x;
    int co  = tid & 127;
    int g   = tid >> 7;            // 2 row groups
    int d   = blockIdx.y;
    int r0  = blockIdx.x * ROWS;

    // x tile with zero halo
    for (int i = tid; i < (ROWS + 2) * (W_ + 2); i += 256){
        int rr = i / (W_ + 2), cc = i % (W_ + 2);
        int hh = r0 - 1 + rr, ww = cc - 1;
        uint4 v = make_uint4(0u, 0u, 0u, 0u);
        if ((unsigned)hh < H_ && (unsigned)ww < W_)
            v = g_xb[(d * H_ + hh) * W_ + ww];
        xs[rr][cc] = v;
    }

    uint4 wr[9];
    #pragma unroll
    for (int t = 0; t < 9; t++)
        wr[t] = g_wb[(d * 9 + t) * COUT_ + co];
    __syncthreads();

    float* outp = out + ((size_t)(d * H_ + r0) * W_) * COUT_ + co;
    #pragma unroll
    for (int pr = 0; pr < ROWS; pr += 2){
        int r = pr + g;                          // rows {g, g+2}
        float* rowp = outp + (size_t)r * W_ * COUT_;
        #pragma unroll 4
        for (int pc = 0; pc < W_; pc++){
            int acc = 0;
            #pragma unroll
            for (int t = 0; t < 9; t++){
                uint4 xv = xs[r + t / 3][pc + t % 3];
                acc += __popc(xv.x ^ wr[t].x);
                acc += __popc(xv.y ^ wr[t].y);
                acc += __popc(xv.z ^ wr[t].z);
                acc += __popc(xv.w ^ wr[t].w);
            }
            rowp[(size_t)pc * COUT_] = (float)(KOFF - 2 * acc);
        }
    }
}

extern "C" void kernel_launch(void* const* d_in, const int* in_sizes, int n_in,
                              void* d_out, int out_size){
    const void* in0 = d_in[0];
    const void* in1 = d_in[1];
    // defensive: identify x vs w (9437184 elems) by size
    if (in_sizes[0] == D_*9*CIN_*COUT_) { const void* t = in0; in0 = in1; in1 = t; }
    const uint8_t* x = (const uint8_t*)in0;
    const float*   w = (const float*)in1;
    float* out = (float*)d_out;

    pack_x_kernel<<<NPIX / 256, 256>>>(x);
    pack_w_kernel<<<D_ * 9, 256>>>(w);
    conv_kernel<<<dim3(H_ / ROWS, D_), 256>>>(out);
}

// round 6
// speedup vs baseline: 1.5788x; 1.5788x over previous
#include <cuda_runtime.h>
#include <stdint.h>

#define D_    64
#define H_    32
#define W_    32
#define CIN_  128
#define COUT_ 128
#define NPIX  (D_*H_*W_)     // 65536
#define KOFF  1152
#define ROWS  4
#define PACKX_BLOCKS (NPIX/256)   // 256
#define PACKW_BLOCKS (D_*9)       // 576

// -------- scratch (no allocations allowed) --------
__device__ uint4 g_xb[NPIX];            // packed x bits: 128 bits / pixel
__device__ uint4 g_wb[D_*9*COUT_];      // packed w bits per (d,tap,cout)

// bytes of v are 0/1: returns b0 | b1<<1 | b2<<2 | b3<<3
__device__ __forceinline__ uint32_t nib(uint32_t v){
    return (v | (v >> 7) | (v >> 14) | (v >> 21)) & 0xFu;
}

// Fused packing kernel. Blocks [0,256): pack x (dtype-probed).
// Blocks [256,832): pack w via smem transpose + ballot.
__global__ __launch_bounds__(256)
void pack_kernel(const uint8_t* __restrict__ x, const float* __restrict__ w){
    __shared__ union {
        struct { float tile[32][129]; uint32_t wword[4][128]; } pw;
        int mode;
    } sm;
    int tid = threadIdx.x;

    if (blockIdx.x < PACKX_BLOCKS){
        // ---- pack x: one thread per pixel, contiguous 128B per thread ----
        if (tid < 32){
            const uint4* p4 = reinterpret_cast<const uint4*>(x);
            int gt1 = 0, nz = 0, bf = 0;
            for (int i = tid; i < 256; i += 32){
                uint4 a = p4[i];
                uint32_t r[4] = {a.x, a.y, a.z, a.w};
                #pragma unroll
                for (int e = 0; e < 4; e++){
                    uint32_t v = r[e];
                    if (v & 0xFEFEFEFEu)            gt1 = 1;  // any byte >1
                    if (v & 0xFFFFFF00u)            nz  = 1;  // nonzero off word-pos
                    if (((v >> 8) & 0xFFu) == 0x3F) bf  = 1;  // bf16 signature
                }
            }
            gt1 = __reduce_or_sync(0xFFFFFFFFu, gt1);
            nz  = __reduce_or_sync(0xFFFFFFFFu, nz);
            bf  = __reduce_or_sync(0xFFFFFFFFu, bf);
            if (tid == 0) sm.mode = (!gt1) ? (nz ? 0 : 1) : (bf ? 3 : 2);
        }
        __syncthreads();
        int mode = sm.mode;            // 0=uint8, 1=int32, 2=float32, 3=bf16
        int p = blockIdx.x * 256 + tid;
        uint32_t wd[4];
        if (mode == 1){                // int32 0/1 (observed)
            const uint4* pi = reinterpret_cast<const uint4*>(x) + (size_t)p * 32;
            #pragma unroll
            for (int k = 0; k < 4; k++){
                uint32_t v = 0;
                #pragma unroll
                for (int q = 0; q < 8; q++){
                    uint4 a = pi[k*8 + q];
                    v |= (a.x ? 1u : 0u) << (q*4 + 0);
                    v |= (a.y ? 1u : 0u) << (q*4 + 1);
                    v |= (a.z ? 1u : 0u) << (q*4 + 2);
                    v |= (a.w ? 1u : 0u) << (q*4 + 3);
                }
                wd[k] = v;
            }
        } else if (mode == 0){         // uint8 bool
            const uint4* px = reinterpret_cast<const uint4*>(x) + (size_t)p * 8;
            #pragma unroll
            for (int k = 0; k < 4; k++){
                uint4 a = px[2*k], b = px[2*k+1];
                wd[k] = nib(a.x)        | (nib(a.y) << 4)  | (nib(a.z) << 8)  | (nib(a.w) << 12)
                      | (nib(b.x) << 16)| (nib(b.y) << 20) | (nib(b.z) << 24) | (nib(b.w) << 28);
            }
        } else if (mode == 2){         // float32 0/1
            const float4* pf = reinterpret_cast<const float4*>(x) + (size_t)p * 32;
            #pragma unroll
            for (int k = 0; k < 4; k++){
                uint32_t v = 0;
                #pragma unroll
                for (int q = 0; q < 8; q++){
                    float4 f = pf[k*8 + q];
                    v |= (f.x != 0.0f ? 1u : 0u) << (q*4 + 0);
                    v |= (f.y != 0.0f ? 1u : 0u) << (q*4 + 1);
                    v |= (f.z != 0.0f ? 1u : 0u) << (q*4 + 2);
                    v |= (f.w != 0.0f ? 1u : 0u) << (q*4 + 3);
                }
                wd[k] = v;
            }
        } else {                       // bf16 0/1
            const uint4* pb = reinterpret_cast<const uint4*>(x) + (size_t)p * 16;
            #pragma unroll
            for (int k = 0; k < 4; k++){
                uint32_t v = 0;
                #pragma unroll
                for (int q = 0; q < 4; q++){
                    uint4 a = pb[k*4 + q];
                    uint32_t r[4] = {a.x, a.y, a.z, a.w};
                    #pragma unroll
                    for (int e = 0; e < 4; e++){
                        v |= ((r[e] & 0x7FFFu)     ? 1u : 0u) << (q*8 + e*2 + 0);
                        v |= ((r[e] & 0x7FFF0000u) ? 1u : 0u) << (q*8 + e*2 + 1);
                    }
                }
                wd[k] = v;
            }
        }
        g_xb[p] = make_uint4(wd[0], wd[1], wd[2], wd[3]);
    } else {
        // ---- pack w: one block per (d,tap); smem transpose + ballot ----
        int dt   = blockIdx.x - PACKX_BLOCKS;   // d*9 + tap
        int lane = tid & 31, warp = tid >> 5;
        const float* wp = w + (size_t)dt * (CIN_ * COUT_);
        #pragma unroll
        for (int chunk = 0; chunk < 4; chunk++){
            __syncthreads();
            #pragma unroll
            for (int e = 0; e < 16; e++){
                int idx = e * 256 + tid;            // 32 cin-rows x 128 cout
                sm.pw.tile[idx >> 7][idx & 127] = wp[chunk * 4096 + idx];
            }
            __syncthreads();
            #pragma unroll
            for (int k = 0; k < 16; k++){
                int c = warp * 16 + k;              // cout; lane = cin bit
                uint32_t b = __ballot_sync(0xFFFFFFFFu, sm.pw.tile[lane][c] != 0.0f);
                if (lane == 0) sm.pw.wword[chunk][c] = b;
            }
        }
        __syncthreads();
        if (tid < 128)
            g_wb[dt * COUT_ + tid] = make_uint4(sm.pw.wword[0][tid], sm.pw.wword[1][tid],
                                                sm.pw.wword[2][tid], sm.pw.wword[3][tid]);
    }
}

// Conv via XOR identity: out = K - 2*sum_taps popc(x ^ w), exact with
// zero-filled halo. R4-proven loop structure; thread co keeps 36 w-words in
// registers; x tile in smem (broadcast LDS.128); coalesced STG.
__global__ __launch_bounds__(256)
void conv_kernel(float* __restrict__ out){
    __shared__ uint4 xs[ROWS + 2][W_ + 2];
    int tid = threadIdx.x;
    int co  = tid & 127;
    int g   = tid >> 7;            // 2 pixel groups
    int d   = blockIdx.y;
    int r0  = blockIdx.x * ROWS;

    // x tile with zero halo
    for (int i = tid; i < (ROWS + 2) * (W_ + 2); i += 256){
        int rr = i / (W_ + 2), cc = i % (W_ + 2);
        int hh = r0 - 1 + rr, ww = cc - 1;
        uint4 v = make_uint4(0u, 0u, 0u, 0u);
        if ((unsigned)hh < H_ && (unsigned)ww < W_)
            v = g_xb[(d * H_ + hh) * W_ + ww];
        xs[rr][cc] = v;
    }

    uint4 wr[9];
    #pragma unroll
    for (int t = 0; t < 9; t++)
        wr[t] = g_wb[(d * 9 + t) * COUT_ + co];
    __syncthreads();

    float* outp = out + ((size_t)(d * H_ + r0) * W_) * COUT_ + co;
    #pragma unroll 2
    for (int p = g; p < ROWS * W_; p += 2){
        int pr = p >> 5, pc = p & 31;
        int acc = 0;
        #pragma unroll
        for (int t = 0; t < 9; t++){
            uint4 xv = xs[pr + t / 3][pc + t % 3];
            acc += __popc(xv.x ^ wr[t].x);
            acc += __popc(xv.y ^ wr[t].y);
            acc += __popc(xv.z ^ wr[t].z);
            acc += __popc(xv.w ^ wr[t].w);
        }
        outp[(size_t)p * COUT_] = (float)(KOFF - 2 * acc);
    }
}

extern "C" void kernel_launch(void* const* d_in, const int* in_sizes, int n_in,
                              void* d_out, int out_size){
    const void* in0 = d_in[0];
    const void* in1 = d_in[1];
    // defensive: identify x vs w (9437184 elems) by size
    if (in_sizes[0] == D_*9*CIN_*COUT_) { const void* t = in0; in0 = in1; in1 = t; }
    const uint8_t* x = (const uint8_t*)in0;
    const float*   w = (const float*)in1;
    float* out = (float*)d_out;

    pack_kernel<<<PACKX_BLOCKS + PACKW_BLOCKS, 256>>>(x, w);
    conv_kernel<<<dim3(H_ / ROWS, D_), 256>>>(out);
}